// round 9
// baseline (speedup 1.0000x reference)
#include <cuda_runtime.h>
#include <cstdint>

#define BB  16
#define NN  4096
#define NP  1024
#define CC  64
#define NSMP 32
#define R2  0.04f

// idx scratch: 16*1024*32 ints = 2 MB
__device__ int g_idx[BB * NP * NSMP];

// Packed f32x2 helpers (Blackwell sm_103a). Same .rn rounding as scalar.
#define ADD2(out, a, b) asm("add.rn.f32x2 %0, %1, %2;" : "=l"(out) : "l"(a), "l"(b))
#define MUL2(out, a, b) asm("mul.rn.f32x2 %0, %1, %2;" : "=l"(out) : "l"(a), "l"(b))
#define UNPK2(lo, hi, in) asm("mov.b64 {%0, %1}, %2;" : "=r"(lo), "=r"(hi) : "l"(in))
#define PK2(out, lo, hi) asm("mov.b64 %0, {%1, %2};" : "=l"(out) : "r"(lo), "r"(hi))

// ---------------------------------------------------------------------------
// Kernel 1: ball query. Grid = 16 x 8 = 128 blocks, 768 threads (24 warps).
// TWO centers per warp share each chunk load (halves smem-crossbar traffic,
// the measured bottleneck). Finished center's section skipped uniformly.
// Pair-granular work stealing over the block's 64 pairs.
// ---------------------------------------------------------------------------
__global__ void __launch_bounds__(768, 1) ball_query_kernel(
    const float* __restrict__ xyz, const float* __restrict__ new_xyz)
{
    __shared__ __align__(16) float xs[NN];
    __shared__ __align__(16) float ys[NN];
    __shared__ __align__(16) float zs[NN];
    __shared__ int s_next;

    const int b   = blockIdx.x >> 3;   // 8 blocks per batch
    const int blk = blockIdx.x & 7;

    if (threadIdx.x == 0) s_next = 24;   // pairs 0..23 statically claimed

    const float* xb = xyz + b * NN * 3;
    for (int t = threadIdx.x; t < NN * 3; t += 768) {
        float v = xb[t];
        int n = t / 3;
        int c = t - n * 3;
        if (c == 0)      xs[n] = v;
        else if (c == 1) ys[n] = v;
        else             zs[n] = v;
    }
    __syncthreads();

    const int warp = threadIdx.x >> 5;
    const int lane = threadIdx.x & 31;
    const unsigned ltmask = (1u << lane) - 1u;

    int pr = warp;   // pair id (0..63): centers 2*pr, 2*pr+1 within block

    #pragma unroll 1
    while (pr < 64) {
        const int npA = (blk << 7) + (pr << 1);
        const float* cA = new_xyz + ((b << 10) + npA) * 3;
        const float* cB = cA + 3;

        uint64_t nAx, nAy, nAz, nBx, nBy, nBz;
        {
            unsigned t0 = __float_as_uint(-cA[0]);
            unsigned t1 = __float_as_uint(-cA[1]);
            unsigned t2 = __float_as_uint(-cA[2]);
            PK2(nAx, t0, t0); PK2(nAy, t1, t1); PK2(nAz, t2, t2);
            t0 = __float_as_uint(-cB[0]);
            t1 = __float_as_uint(-cB[1]);
            t2 = __float_as_uint(-cB[2]);
            PK2(nBx, t0, t0); PK2(nBy, t1, t1); PK2(nBz, t2, t2);
        }

        int cntA = 0, cntB = 0;
        int firstA = 0, firstB = 0;
        int* orowA = g_idx + (((b << 10) + npA) << 5);
        int* orowB = orowA + NSMP;

        #pragma unroll 1
        for (int chunk = 0; chunk < NN / 128; chunk++) {
            const int base = (chunk << 7) + (lane << 2);
            ulonglong2 xv = *(const ulonglong2*)(xs + base);   // pts (0,1),(2,3)
            ulonglong2 yv = *(const ulonglong2*)(ys + base);
            ulonglong2 zv = *(const ulonglong2*)(zs + base);

            // ---- center A (skipped uniformly once full) ----
            if (cntA < NSMP) {
                uint64_t dx0, dy0, dz0, dx1, dy1, dz1, s0, s1;
                ADD2(dx0, xv.x, nAx);  ADD2(dx1, xv.y, nAx);
                ADD2(dy0, yv.x, nAy);  ADD2(dy1, yv.y, nAy);
                ADD2(dz0, zv.x, nAz);  ADD2(dz1, zv.y, nAz);
                MUL2(dx0, dx0, dx0);   MUL2(dx1, dx1, dx1);
                MUL2(dy0, dy0, dy0);   MUL2(dy1, dy1, dy1);
                MUL2(dz0, dz0, dz0);   MUL2(dz1, dz1, dz1);
                ADD2(s0, dx0, dy0);    ADD2(s1, dx1, dy1);
                ADD2(s0, s0, dz0);     ADD2(s1, s1, dz1);
                unsigned u0, u1, u2, u3;
                UNPK2(u0, u1, s0);
                UNPK2(u2, u3, s1);
                bool m0 = __uint_as_float(u0) < R2;
                bool m1 = __uint_as_float(u1) < R2;
                bool m2 = __uint_as_float(u2) < R2;
                bool m3 = __uint_as_float(u3) < R2;
                const unsigned b0 = __ballot_sync(0xffffffffu, m0);
                const unsigned b1 = __ballot_sync(0xffffffffu, m1);
                const unsigned b2 = __ballot_sync(0xffffffffu, m2);
                const unsigned b3 = __ballot_sync(0xffffffffu, m3);
                if (cntA == 0) {
                    unsigned any = b0 | b1 | b2 | b3;
                    if (any) {
                        int f = 1 << 30;
                        if (b0) f = min(f, ((__ffs(b0) - 1) << 2) + 0);
                        if (b1) f = min(f, ((__ffs(b1) - 1) << 2) + 1);
                        if (b2) f = min(f, ((__ffs(b2) - 1) << 2) + 2);
                        if (b3) f = min(f, ((__ffs(b3) - 1) << 2) + 3);
                        firstA = (chunk << 7) + f;
                    }
                }
                int pre = __popc(b0 & ltmask) + __popc(b1 & ltmask)
                        + __popc(b2 & ltmask) + __popc(b3 & ltmask);
                int s;
                s = cntA + pre; pre += (int)m0;
                if (m0 & (s < NSMP)) orowA[s] = base + 0;
                s = cntA + pre; pre += (int)m1;
                if (m1 & (s < NSMP)) orowA[s] = base + 1;
                s = cntA + pre; pre += (int)m2;
                if (m2 & (s < NSMP)) orowA[s] = base + 2;
                s = cntA + pre; pre += (int)m3;
                if (m3 & (s < NSMP)) orowA[s] = base + 3;
                cntA += __popc(b0) + __popc(b1) + __popc(b2) + __popc(b3);
            }

            // ---- center B (skipped uniformly once full) ----
            if (cntB < NSMP) {
                uint64_t dx0, dy0, dz0, dx1, dy1, dz1, s0, s1;
                ADD2(dx0, xv.x, nBx);  ADD2(dx1, xv.y, nBx);
                ADD2(dy0, yv.x, nBy);  ADD2(dy1, yv.y, nBy);
                ADD2(dz0, zv.x, nBz);  ADD2(dz1, zv.y, nBz);
                MUL2(dx0, dx0, dx0);   MUL2(dx1, dx1, dx1);
                MUL2(dy0, dy0, dy0);   MUL2(dy1, dy1, dy1);
                MUL2(dz0, dz0, dz0);   MUL2(dz1, dz1, dz1);
                ADD2(s0, dx0, dy0);    ADD2(s1, dx1, dy1);
                ADD2(s0, s0, dz0);     ADD2(s1, s1, dz1);
                unsigned u0, u1, u2, u3;
                UNPK2(u0, u1, s0);
                UNPK2(u2, u3, s1);
                bool m0 = __uint_as_float(u0) < R2;
                bool m1 = __uint_as_float(u1) < R2;
                bool m2 = __uint_as_float(u2) < R2;
                bool m3 = __uint_as_float(u3) < R2;
                const unsigned b0 = __ballot_sync(0xffffffffu, m0);
                const unsigned b1 = __ballot_sync(0xffffffffu, m1);
                const unsigned b2 = __ballot_sync(0xffffffffu, m2);
                const unsigned b3 = __ballot_sync(0xffffffffu, m3);
                if (cntB == 0) {
                    unsigned any = b0 | b1 | b2 | b3;
                    if (any) {
                        int f = 1 << 30;
                        if (b0) f = min(f, ((__ffs(b0) - 1) << 2) + 0);
                        if (b1) f = min(f, ((__ffs(b1) - 1) << 2) + 1);
                        if (b2) f = min(f, ((__ffs(b2) - 1) << 2) + 2);
                        if (b3) f = min(f, ((__ffs(b3) - 1) << 2) + 3);
                        firstB = (chunk << 7) + f;
                    }
                }
                int pre = __popc(b0 & ltmask) + __popc(b1 & ltmask)
                        + __popc(b2 & ltmask) + __popc(b3 & ltmask);
                int s;
                s = cntB + pre; pre += (int)m0;
                if (m0 & (s < NSMP)) orowB[s] = base + 0;
                s = cntB + pre; pre += (int)m1;
                if (m1 & (s < NSMP)) orowB[s] = base + 1;
                s = cntB + pre; pre += (int)m2;
                if (m2 & (s < NSMP)) orowB[s] = base + 2;
                s = cntB + pre; pre += (int)m3;
                if (m3 & (s < NSMP)) orowB[s] = base + 3;
                cntB += __popc(b0) + __popc(b1) + __popc(b2) + __popc(b3);
            }

            if ((cntA >= NSMP) & (cntB >= NSMP)) break;
        }

        if (cntA < NSMP)
            for (int s = cntA + lane; s < NSMP; s += 32) orowA[s] = firstA;
        if (cntB < NSMP)
            for (int s = cntB + lane; s < NSMP; s += 32) orowB[s] = firstB;

        // grab next pair
        int nc;
        if (lane == 0) nc = atomicAdd(&s_next, 1);
        pr = __shfl_sync(0xffffffffu, nc, 0);
    }
}

// ---------------------------------------------------------------------------
// Kernel 2 (unchanged R6 winner): gather + group. Grid = 272 blocks,
// 512 threads, 64 KB smem -> 2 CTAs/SM. Register-transpose staging,
// gather 4x LDS.128, register transpose, 1x STG.128 per channel.
// ---------------------------------------------------------------------------
__global__ void __launch_bounds__(512) group_kernel(
    const float* __restrict__ xyz, const float* __restrict__ new_xyz,
    const float* __restrict__ points, float* __restrict__ out)
{
    extern __shared__ float sm[];   // 4 * 4096 floats = 64 KB
    const int tile = blockIdx.x % 17;
    const int b    = blockIdx.x / 17;
    const int tid  = threadIdx.x;
    const int warp = tid >> 5;
    const int lane = tid & 31;
    const int S    = NP * NSMP;

    const int sub  = lane >> 3;          // center within group of 4
    const int soff = (lane & 7) << 2;    // sample offset (0,4,...,28)

    if (tile < 16) {
        // stage 4 channels: thread owns point n, 4 coalesced LDG.32 + 1 STS.128
        const float* pb = points + (b * CC + tile * 4) * NN;
        #pragma unroll
        for (int j = 0; j < 8; j++) {
            int n = tid + j * 512;
            float4 v;
            v.x = pb[0 * NN + n];
            v.y = pb[1 * NN + n];
            v.z = pb[2 * NN + n];
            v.w = pb[3 * NN + n];
            *(float4*)(sm + (n << 2)) = v;
        }
        __syncthreads();

        const int obase = (b * 67 + 3 + tile * 4) * S;
        int g = warp;                         // group of 4 centers, 256 groups
        const int np0 = (g << 2) + sub;
        int4 id = *(const int4*)(g_idx + (((b << 10) + np0) << 5) + soff);
        #pragma unroll 1
        while (g < 256) {
            const int gn = g + 16;
            int4 idn;
            if (gn < 256) {
                const int npn = (gn << 2) + sub;
                idn = *(const int4*)(g_idx + (((b << 10) + npn) << 5) + soff);
            }

            const float4 p0 = *(const float4*)(sm + (id.x << 2));
            const float4 p1 = *(const float4*)(sm + (id.y << 2));
            const float4 p2 = *(const float4*)(sm + (id.z << 2));
            const float4 p3 = *(const float4*)(sm + (id.w << 2));

            float4* o = (float4*)(out + obase + (g << 7) + (lane << 2));
            const int S4 = S >> 2;
            float4 t0 = make_float4(p0.x, p1.x, p2.x, p3.x);
            float4 t1 = make_float4(p0.y, p1.y, p2.y, p3.y);
            float4 t2 = make_float4(p0.z, p1.z, p2.z, p3.z);
            float4 t3 = make_float4(p0.w, p1.w, p2.w, p3.w);
            __stcs(o + 0 * S4, t0);
            __stcs(o + 1 * S4, t1);
            __stcs(o + 2 * S4, t2);
            __stcs(o + 3 * S4, t3);

            id = idn;
            g = gn;
        }
    } else {
        // xyz tile: thread owns point n, 3 LDG.32 + 1 STS.128
        const float* xb = xyz + b * NN * 3;
        #pragma unroll
        for (int j = 0; j < 8; j++) {
            int n = tid + j * 512;
            float4 v;
            v.x = xb[n * 3 + 0];
            v.y = xb[n * 3 + 1];
            v.z = xb[n * 3 + 2];
            v.w = 0.0f;
            *(float4*)(sm + (n << 2)) = v;
        }
        __syncthreads();

        const int obase = (b * 67) * S;
        int g = warp;
        const int np0 = (g << 2) + sub;
        int4 id = *(const int4*)(g_idx + (((b << 10) + np0) << 5) + soff);
        #pragma unroll 1
        while (g < 256) {
            const int gn = g + 16;
            int4 idn;
            if (gn < 256) {
                const int npn = (gn << 2) + sub;
                idn = *(const int4*)(g_idx + (((b << 10) + npn) << 5) + soff);
            }

            const int np = (g << 2) + sub;
            const float* c3 = new_xyz + ((b << 10) + np) * 3;
            const float cx = __ldg(c3 + 0);
            const float cy = __ldg(c3 + 1);
            const float cz = __ldg(c3 + 2);

            const float4 p0 = *(const float4*)(sm + (id.x << 2));
            const float4 p1 = *(const float4*)(sm + (id.y << 2));
            const float4 p2 = *(const float4*)(sm + (id.z << 2));
            const float4 p3 = *(const float4*)(sm + (id.w << 2));

            float4* o = (float4*)(out + obase + (g << 7) + (lane << 2));
            const int S4 = S >> 2;
            float4 t0 = make_float4(p0.x - cx, p1.x - cx, p2.x - cx, p3.x - cx);
            float4 t1 = make_float4(p0.y - cy, p1.y - cy, p2.y - cy, p3.y - cy);
            float4 t2 = make_float4(p0.z - cz, p1.z - cz, p2.z - cz, p3.z - cz);
            __stcs(o + 0 * S4, t0);
            __stcs(o + 1 * S4, t1);
            __stcs(o + 2 * S4, t2);

            id = idn;
            g = gn;
        }
    }
}

extern "C" void kernel_launch(void* const* d_in, const int* in_sizes, int n_in,
                              void* d_out, int out_size)
{
    const float* xyz = nullptr;
    const float* new_xyz = nullptr;
    const float* points = nullptr;
    for (int i = 0; i < n_in; i++) {
        if (in_sizes[i] == BB * NN * 3)      xyz     = (const float*)d_in[i];
        else if (in_sizes[i] == BB * NP * 3) new_xyz = (const float*)d_in[i];
        else if (in_sizes[i] == BB * CC * NN) points = (const float*)d_in[i];
    }
    float* out = (float*)d_out;

    cudaFuncSetAttribute(group_kernel, cudaFuncAttributeMaxDynamicSharedMemorySize, 65536);

    ball_query_kernel<<<BB * 8, 768>>>(xyz, new_xyz);
    group_kernel<<<BB * 17, 512, 65536>>>(xyz, new_xyz, points, out);
}